// round 1
// baseline (speedup 1.0000x reference)
#include <cuda_runtime.h>

typedef unsigned long long ull;

#define T_LEN 8192
#define NLAG  64

// ---- packed f32x2 helpers (sm_100+ PTX) ----
__device__ __forceinline__ ull pk(float lo, float hi) {
    ull r;
    asm("mov.b64 %0, {%1, %2};" : "=l"(r) : "f"(lo), "f"(hi));
    return r;
}
__device__ __forceinline__ void fma2(ull& d, ull a, ull b) {
    asm("fma.rn.f32x2 %0, %1, %2, %0;" : "+l"(d) : "l"(a), "l"(b));
}
__device__ __forceinline__ float pksum(ull v) {
    float lo, hi;
    asm("mov.b64 {%0, %1}, %2;" : "=f"(lo), "=f"(hi) : "l"(v));
    return lo + hi;
}

__global__ __launch_bounds__(256, 2)
void autocorr_kernel(const float* __restrict__ X, float* __restrict__ out)
{
    // skewed row storage: phys(i) = i + (i>>4); max i = 8255 -> phys 8770
    __shared__ float sm[8772];
    __shared__ float red[8][16];
    __shared__ float wsum[8], wsq[8];
    __shared__ float stats[2];   // [0]=mean, [1]=1/var0

    const int tid = threadIdx.x;
    const int b   = blockIdx.x;
    const float4* Xr = reinterpret_cast<const float4*>(X + (size_t)b * T_LEN);

    // ---------------- Phase 1: load, mean & sumsq reduce, centered skewed store
    float4 xv[8];
    float s = 0.f, q = 0.f;
#pragma unroll
    for (int r = 0; r < 8; ++r) {
        xv[r] = Xr[tid + r * 256];
        s += xv[r].x + xv[r].y + xv[r].z + xv[r].w;
        q += xv[r].x * xv[r].x + xv[r].y * xv[r].y
           + xv[r].z * xv[r].z + xv[r].w * xv[r].w;
    }
#pragma unroll
    for (int o = 16; o > 0; o >>= 1) {
        s += __shfl_xor_sync(0xffffffffu, s, o);
        q += __shfl_xor_sync(0xffffffffu, q, o);
    }
    if ((tid & 31) == 0) { wsum[tid >> 5] = s; wsq[tid >> 5] = q; }
    __syncthreads();
    if (tid == 0) {
        float S = 0.f, Q = 0.f;
#pragma unroll
        for (int i = 0; i < 8; ++i) { S += wsum[i]; Q += wsq[i]; }
        float mean = S * (1.f / (float)T_LEN);
        stats[0] = mean;
        // var0 = sum (x-mean)^2 = Q - T*mean^2   (the 1/T in reference cancels in the ratio)
        stats[1] = 1.f / (Q - (float)T_LEN * mean * mean);
    }
    __syncthreads();
    const float mean = stats[0];

#pragma unroll
    for (int r = 0; r < 8; ++r) {
        int i0 = (tid + r * 256) * 4;
        int p  = i0 + (i0 >> 4);           // i0 % 16 in {0,4,8,12}: 4 elems share skew
        sm[p    ] = xv[r].x - mean;
        sm[p + 1] = xv[r].y - mean;
        sm[p + 2] = xv[r].z - mean;
        sm[p + 3] = xv[r].w - mean;
    }
    if (tid < NLAG) {                       // zero pad tail -> boundary handled for free
        int i = T_LEN + tid;
        sm[i + (i >> 4)] = 0.f;
    }
    __syncthreads();

    // ---------------- Phase 2: lag-group register-tiled correlation (f32x2)
    // group g handles lags k0..k0+15, k0 = 1 + 16g  (k0 mod 16 == 1 for all groups)
    const int g  = tid >> 6;
    const int tt = tid & 63;
    const int k0 = 1 + g * 16;
    const int woff = k0 + (k0 >> 4);

    ull acc[16];
#pragma unroll
    for (int i = 0; i < 16; ++i) acc[i] = 0ull;

#pragma unroll 1
    for (int seg = 0; seg < 8; ++seg) {
        // logical t0 = seg*1024 + tt*16 ; skewed base = t0 + (t0>>4)
        const int base = tt * 17 + seg * 1088;

        float a[16];
#pragma unroll
        for (int j = 0; j < 16; ++j) a[j] = sm[base + j];   // stride-17 across lanes: CF

        const int wb = base + woff;
        float w[31];
#pragma unroll
        for (int j = 0; j < 31; ++j)
            w[j] = sm[wb + j + ((j >= 15) ? 1 : 0)];        // skew boundary at j==15

        ull A2[8];
#pragma unroll
        for (int m = 0; m < 8; ++m) A2[m] = pk(a[2 * m], a[2 * m + 1]);
        ull E[15];
#pragma unroll
        for (int m = 0; m < 15; ++m) E[m] = pk(w[2 * m], w[2 * m + 1]);
        ull O[15];
#pragma unroll
        for (int m = 0; m < 15; ++m) O[m] = pk(w[2 * m + 1], w[2 * m + 2]);

        // even dk = 2*d2: pairs {w[2m+dk], w[2m+dk+1]} = E[m+d2]
#pragma unroll
        for (int d2 = 0; d2 < 8; ++d2) {
#pragma unroll
            for (int m = 0; m < 8; ++m) fma2(acc[2 * d2], A2[m], E[m + d2]);
        }
        // odd dk = 2*d2+1: pairs = O[m+d2]
#pragma unroll
        for (int d2 = 0; d2 < 8; ++d2) {
#pragma unroll
            for (int m = 0; m < 8; ++m) fma2(acc[2 * d2 + 1], A2[m], O[m + d2]);
        }
    }

    // ---------------- Phase 3: reduce across threads, normalize, store
    float v[16];
#pragma unroll
    for (int i = 0; i < 16; ++i) v[i] = pksum(acc[i]);
#pragma unroll
    for (int o = 16; o > 0; o >>= 1) {
#pragma unroll
        for (int i = 0; i < 16; ++i)
            v[i] += __shfl_xor_sync(0xffffffffu, v[i], o);
    }
    if ((tid & 31) == 0) {
        int wid = tid >> 5;
#pragma unroll
        for (int i = 0; i < 16; ++i) red[wid][i] = v[i];
    }
    __syncthreads();
    if (tid < 64) {
        int gg = tid >> 4, dk = tid & 15;       // lag = 16*gg + dk + 1 -> out col = tid
        float sum = red[2 * gg][dk] + red[2 * gg + 1][dk];
        out[(size_t)b * NLAG + tid] = sum * stats[1];
    }
}

extern "C" void kernel_launch(void* const* d_in, const int* in_sizes, int n_in,
                              void* d_out, int out_size)
{
    const float* X = (const float*)d_in[0];
    float* out = (float*)d_out;
    const int B = in_sizes[0] / T_LEN;   // 4096
    autocorr_kernel<<<B, 256>>>(X, out);
}

// round 2
// speedup vs baseline: 1.0352x; 1.0352x over previous
#include <cuda_runtime.h>

typedef unsigned long long ull;

#define T_LEN 8192
#define NLAG  64

// skew2 layout: phys(i) = i + 2*(i>>4)  (stride 18 per 16-elem chunk,
// parity-preserving -> logical-even pairs are 8B-aligned LDS.64)
#define PHYS_MAX 9288   // phys(8255)=9285, padded

// ---- packed f32x2 helpers (sm_100+ PTX) ----
__device__ __forceinline__ ull pk(float lo, float hi) {
    ull r;
    asm("mov.b64 %0, {%1, %2};" : "=l"(r) : "f"(lo), "f"(hi));
    return r;
}
__device__ __forceinline__ void fma2(ull& d, ull a, ull b) {
    asm("fma.rn.f32x2 %0, %1, %2, %0;" : "+l"(d) : "l"(a), "l"(b));
}
__device__ __forceinline__ float pksum(ull v) {
    float lo, hi;
    asm("mov.b64 {%0, %1}, %2;" : "=f"(lo), "=f"(hi) : "l"(v));
    return lo + hi;
}

// One lag-group: lags K0..K0+15 (K0 = 1+16g, odd). All w-pair shared-memory
// offsets are compile-time constants -> LDS immediates, no address ALU.
template<int K0>
__device__ __forceinline__ void corr_group(const float* __restrict__ sm, int tt,
                                           ull* __restrict__ acc,
                                           float* __restrict__ eacc)
{
#pragma unroll 1
    for (int seg = 0; seg < 8; ++seg) {
        const int base = seg * 1152 + tt * 18;   // phys(seg*1024 + tt*16)

        // ---- A: 16 contiguous positions, 8 aligned pairs (LDS.64, CF) ----
        float2 A[8];
#pragma unroll
        for (int m = 0; m < 8; ++m)
            A[m] = *reinterpret_cast<const float2*>(&sm[base + 2 * m]);
        ull Au[8];
#pragma unroll
        for (int m = 0; m < 8; ++m) Au[m] = pk(A[m].x, A[m].y);
        const float a0  = A[0].x;
        const float a15 = A[7].y;

        // ---- W: 15 aligned pairs covering w[1..30]; pair r starts at w-index 2r+1
        // logical u = K0+2r+1 (even), phys offset = u + 2*(u>>4), never crosses skew
        float2 W[15];
#pragma unroll
        for (int r = 0; r < 15; ++r) {
            const int u = K0 + 2 * r + 1;
            W[r] = *reinterpret_cast<const float2*>(&sm[base + u + 2 * (u >> 4)]);
        }
        ull Wu[15];
#pragma unroll
        for (int r = 0; r < 15; ++r) Wu[r] = pk(W[r].x, W[r].y);
        const float w0 = sm[base + K0 + 2 * (K0 >> 4)];   // w[0] scalar

        // ---- odd lags dk=2e+1: aligned A-pairs x W-pairs ----
#pragma unroll
        for (int m = 0; m < 8; ++m)
#pragma unroll
            for (int e = 0; e < 8; ++e)
                fma2(acc[2 * e + 1], Au[m], Wu[m + e]);

        // ---- even lags dk=2e: shifted A-pairs (packed) x same W-pairs + edges
        ull Apu[7];
#pragma unroll
        for (int m = 0; m < 7; ++m) Apu[m] = pk(A[m].y, A[m + 1].x);
#pragma unroll
        for (int m = 0; m < 7; ++m)
#pragma unroll
            for (int e = 0; e < 8; ++e)
                fma2(acc[2 * e], Apu[m], Wu[m + e]);
#pragma unroll
        for (int e = 0; e < 8; ++e) {
            const float wE = (e == 0) ? w0 : W[e - 1].y;   // w[2e]
            const float wO = W[e + 7].x;                   // w[15+2e]
            eacc[e] += a0 * wE + a15 * wO;
        }
    }
}

__global__ __launch_bounds__(256, 2)
void autocorr_kernel(const float* __restrict__ X, float* __restrict__ out)
{
    __shared__ __align__(16) float sm[PHYS_MAX];
    __shared__ float red[8][16];
    __shared__ float wsum[8], wsq[8];
    __shared__ float stats[2];   // [0]=mean, [1]=1/var0

    const int tid = threadIdx.x;
    const int b   = blockIdx.x;
    const float4* Xr = reinterpret_cast<const float4*>(X + (size_t)b * T_LEN);

    // ---------------- Phase 1: load, mean & sumsq, centered skewed store
    float4 xv[8];
    float s = 0.f, q = 0.f;
#pragma unroll
    for (int r = 0; r < 8; ++r) {
        xv[r] = Xr[tid + r * 256];
        s += xv[r].x + xv[r].y + xv[r].z + xv[r].w;
        q += xv[r].x * xv[r].x + xv[r].y * xv[r].y
           + xv[r].z * xv[r].z + xv[r].w * xv[r].w;
    }
#pragma unroll
    for (int o = 16; o > 0; o >>= 1) {
        s += __shfl_xor_sync(0xffffffffu, s, o);
        q += __shfl_xor_sync(0xffffffffu, q, o);
    }
    if ((tid & 31) == 0) { wsum[tid >> 5] = s; wsq[tid >> 5] = q; }
    __syncthreads();
    if (tid == 0) {
        float S = 0.f, Q = 0.f;
#pragma unroll
        for (int i = 0; i < 8; ++i) { S += wsum[i]; Q += wsq[i]; }
        float mean = S * (1.f / (float)T_LEN);
        stats[0] = mean;
        stats[1] = 1.f / (Q - (float)T_LEN * mean * mean);  // 1/T cancels in ratio
    }
    __syncthreads();
    const float mean = stats[0];

#pragma unroll
    for (int r = 0; r < 8; ++r) {
        int i0 = (tid + r * 256) * 4;
        int p  = i0 + 2 * (i0 >> 4);        // all 4 elems share the skew (i0%16 in {0,4,8,12})
        *reinterpret_cast<float2*>(&sm[p])     = make_float2(xv[r].x - mean, xv[r].y - mean);
        *reinterpret_cast<float2*>(&sm[p + 2]) = make_float2(xv[r].z - mean, xv[r].w - mean);
    }
    if (tid < NLAG) {                       // zero pad -> t<T-k bound handled for free
        int i = T_LEN + tid;
        sm[i + 2 * (i >> 4)] = 0.f;
    }
    __syncthreads();

    // ---------------- Phase 2: lag-group register-tiled correlation
    const int g  = tid >> 6;
    const int tt = tid & 63;

    ull acc[16];
#pragma unroll
    for (int i = 0; i < 16; ++i) acc[i] = 0ull;
    float eacc[8];
#pragma unroll
    for (int i = 0; i < 8; ++i) eacc[i] = 0.f;

    switch (g) {
        case 0: corr_group<1 >(sm, tt, acc, eacc); break;
        case 1: corr_group<17>(sm, tt, acc, eacc); break;
        case 2: corr_group<33>(sm, tt, acc, eacc); break;
        default: corr_group<49>(sm, tt, acc, eacc); break;
    }

    // ---------------- Phase 3: reduce, normalize, store
    float v[16];
#pragma unroll
    for (int i = 0; i < 16; ++i) v[i] = pksum(acc[i]);
#pragma unroll
    for (int e = 0; e < 8; ++e) v[2 * e] += eacc[e];
#pragma unroll
    for (int o = 16; o > 0; o >>= 1) {
#pragma unroll
        for (int i = 0; i < 16; ++i)
            v[i] += __shfl_xor_sync(0xffffffffu, v[i], o);
    }
    if ((tid & 31) == 0) {
        int wid = tid >> 5;
#pragma unroll
        for (int i = 0; i < 16; ++i) red[wid][i] = v[i];
    }
    __syncthreads();
    if (tid < 64) {
        int gg = tid >> 4, dk = tid & 15;   // lag = 16*gg + dk + 1 -> out col = tid
        float sum = red[2 * gg][dk] + red[2 * gg + 1][dk];
        out[(size_t)b * NLAG + tid] = sum * stats[1];
    }
}

extern "C" void kernel_launch(void* const* d_in, const int* in_sizes, int n_in,
                              void* d_out, int out_size)
{
    const float* X = (const float*)d_in[0];
    float* out = (float*)d_out;
    const int B = in_sizes[0] / T_LEN;   // 4096
    autocorr_kernel<<<B, 256>>>(X, out);
}